// round 14
// baseline (speedup 1.0000x reference)
#include <cuda_runtime.h>
#include <cuda_fp16.h>
#include <cstdint>

#define NN 50000
#define NE 800000

// ---------------- device scratch (zero-initialized at load; K3 restores zeros) ----------------
__device__ __half g_nmh[(size_t)NN * 128]; // fp16: [n][0:64]=x@W1a+b1, [n][64:128]=x@W1b
__device__ float  g_hsum[(size_t)NN * 64]; // fp32 per-node sum of relu(h)
__device__ float  g_deg[NN];               // per-node edge count

// ---------------- helpers ----------------
__device__ __forceinline__ uint32_t f2tf32(float f) {
    uint32_t r;
    asm("cvt.rna.tf32.f32 %0, %1;" : "=r"(r) : "f"(f));
    return r;
}
__device__ __forceinline__ void mma_tf32(float c[4],
                                         uint32_t a0, uint32_t a1, uint32_t a2, uint32_t a3,
                                         uint32_t b0, uint32_t b1) {
    asm volatile(
        "mma.sync.aligned.m16n8k8.row.col.f32.tf32.tf32.f32 "
        "{%0,%1,%2,%3}, {%4,%5,%6,%7}, {%8,%9}, {%0,%1,%2,%3};"
        : "+f"(c[0]), "+f"(c[1]), "+f"(c[2]), "+f"(c[3])
        : "r"(a0), "r"(a1), "r"(a2), "r"(a3), "r"(b0), "r"(b1));
}
__device__ __forceinline__ void red_add_v4(float* p, float a, float b, float c, float d) {
    asm volatile("red.global.add.v4.f32 [%0], {%1, %2, %3, %4};"
        :: "l"(p), "f"(a), "f"(b), "f"(c), "f"(d) : "memory");
}
__device__ __forceinline__ void red_add_f32(float* p, float v) {
    asm volatile("red.global.add.f32 [%0], %1;" :: "l"(p), "f"(v) : "memory");
}

// ================= K1: g_nmh = fp16(x @ [W1a|W1b] (+b1)); two N=64 passes, low regs =================
__global__ __launch_bounds__(256, 3)
void k1_kernel(const float* __restrict__ x, const float* __restrict__ W1,
               const float* __restrict__ b1, int M) {
    __shared__ uint32_t Ws[64 * 136];
    const int tid = threadIdx.x, lane = tid & 31, wid = tid >> 5;
    const int g = lane >> 2, tg = lane & 3;
    const int m0 = blockIdx.x * 128;

    for (int idx = tid; idx < 64 * 128; idx += 256) {
        int k = idx >> 7, n = idx & 127;
        float w = (n < 64) ? W1[k * 64 + n] : W1[(64 + k) * 64 + (n - 64)];
        Ws[k * 136 + n] = f2tf32(w);
    }
    __syncthreads();

    const int rb = wid * 16;
    const int r0 = m0 + rb + g, r1 = r0 + 8;
    const float* xr0 = x + (size_t)(r0 < M ? r0 : M - 1) * 64;
    const float* xr1 = x + (size_t)(r1 < M ? r1 : M - 1) * 64;

    #pragma unroll
    for (int half = 0; half < 2; half++) {
        // reload fragments per pass (2nd pass hits L2) to keep regs low
        uint32_t afr[8][4];
        #pragma unroll
        for (int kt = 0; kt < 8; kt++) {
            const int k0 = kt * 8;
            afr[kt][0] = f2tf32(__ldg(xr0 + k0 + tg));
            afr[kt][1] = f2tf32(__ldg(xr1 + k0 + tg));
            afr[kt][2] = f2tf32(__ldg(xr0 + k0 + tg + 4));
            afr[kt][3] = f2tf32(__ldg(xr1 + k0 + tg + 4));
        }

        float acc[8][4];
        #pragma unroll
        for (int nt = 0; nt < 8; nt++) acc[nt][0] = acc[nt][1] = acc[nt][2] = acc[nt][3] = 0.f;

        #pragma unroll
        for (int kt = 0; kt < 8; kt++) {
            const int k0 = kt * 8;
            #pragma unroll
            for (int nt = 0; nt < 8; nt++) {
                uint32_t b0 = Ws[(k0 + tg) * 136 + half * 64 + 8 * nt + g];
                uint32_t b1v = Ws[(k0 + tg + 4) * 136 + half * 64 + 8 * nt + g];
                mma_tf32(acc[nt], afr[kt][0], afr[kt][1], afr[kt][2], afr[kt][3], b0, b1v);
            }
        }
        #pragma unroll
        for (int nt = 0; nt < 8; nt++) {
            const int col = half * 64 + 8 * nt + 2 * tg;
            float e0 = 0.f, e1 = 0.f;
            if (half == 0) { e0 = __ldg(b1 + (col & 63)); e1 = __ldg(b1 + (col & 63) + 1); }
            if (r0 < M)
                *reinterpret_cast<__half2*>(g_nmh + (size_t)r0 * 128 + col)
                    = __floats2half2_rn(acc[nt][0] + e0, acc[nt][1] + e1);
            if (r1 < M)
                *reinterpret_cast<__half2*>(g_nmh + (size_t)r1 * 128 + col)
                    = __floats2half2_rn(acc[nt][2] + e0, acc[nt][3] + e1);
        }
    }
}

// ================= K2: h = relu(pre[src]+post[dst]+ea@W1e) -> fp32 scatter + deg =================
// Gather LDGs issued FIRST (prefetch), MMA phase hides their latency.
// smem words: Aea[128*20] | Wes[16*136] | AccH[128*72 halves = 4608 w]
#define AEA_O  0
#define WES_O  (128 * 20)
#define ACCH_O (WES_O + 16 * 136)
#define K2_SMEM ((ACCH_O + 4608) * 4)   // 37376 B
__global__ __launch_bounds__(256, 2)
void k2_kernel(const int* __restrict__ ei, const float* __restrict__ ea,
               const float* __restrict__ W1, int E) {
    extern __shared__ float sm[];
    uint32_t* Aea = reinterpret_cast<uint32_t*>(sm) + AEA_O;
    uint32_t* Wes = reinterpret_cast<uint32_t*>(sm) + WES_O;
    __half*   AccH = reinterpret_cast<__half*>(sm + ACCH_O);

    const int tid = threadIdx.x, lane = tid & 31, wid = tid >> 5;
    const int g = lane >> 2, tg = lane & 3;
    const int e0 = blockIdx.x * 128;

    // ---- prefetch: indices then pre/post gathers, issued before any other phase ----
    const int rr = tid >> 4;              // 0..15 (row group for pass 2)
    const int c4 = (tid & 15) * 4;        // col quad for pass 2

    int srcs[8], dsts[8];
    #pragma unroll
    for (int p = 0; p < 8; p++) {
        int e = e0 + p * 16 + rr;
        int ec = e < E ? e : E - 1;
        srcs[p] = __ldg(ei + ec);
        dsts[p] = __ldg(ei + E + ec);
    }
    uint2 preu[8], postu[8];
    #pragma unroll
    for (int p = 0; p < 8; p++)
        preu[p]  = __ldg(reinterpret_cast<const uint2*>(g_nmh + (size_t)srcs[p] * 128 + c4));
    #pragma unroll
    for (int p = 0; p < 8; p++)
        postu[p] = __ldg(reinterpret_cast<const uint2*>(g_nmh + (size_t)dsts[p] * 128 + 64 + c4));

    // ---- stage ea (tf32) + W1e while gathers are in flight ----
    #pragma unroll
    for (int p = 0; p < 2; p++) {
        int q = tid + 256 * p;            // 0..511
        int r = q >> 2, c = (q & 3) * 4;
        int e = e0 + r;
        float4 v = (e < E) ? __ldg(reinterpret_cast<const float4*>(ea + (size_t)e * 16 + c))
                           : make_float4(0.f, 0.f, 0.f, 0.f);
        uint4 u; u.x = f2tf32(v.x); u.y = f2tf32(v.y); u.z = f2tf32(v.z); u.w = f2tf32(v.w);
        *reinterpret_cast<uint4*>(Aea + r * 20 + c) = u;
    }
    for (int idx = tid; idx < 16 * 64; idx += 256) {
        int k = idx >> 6, n = idx & 63;
        Wes[k * 136 + n] = f2tf32(W1[(128 + k) * 64 + n]);
    }
    __syncthreads();

    // ---- tiny MMA: acc = ea[128x16] @ W1e[16x64], stored fp16 ----
    const int rb = wid * 16;
    float acc[8][4];
    #pragma unroll
    for (int nt = 0; nt < 8; nt++) acc[nt][0] = acc[nt][1] = acc[nt][2] = acc[nt][3] = 0.f;
    #pragma unroll
    for (int kt = 0; kt < 2; kt++) {
        const int k0 = kt * 8;
        uint32_t a0 = Aea[(rb + g) * 20 + k0 + tg];
        uint32_t a1 = Aea[(rb + g + 8) * 20 + k0 + tg];
        uint32_t a2 = Aea[(rb + g) * 20 + k0 + tg + 4];
        uint32_t a3 = Aea[(rb + g + 8) * 20 + k0 + tg + 4];
        #pragma unroll
        for (int nt = 0; nt < 8; nt++) {
            uint32_t b0 = Wes[(k0 + tg) * 136 + 8 * nt + g];
            uint32_t b1v = Wes[(k0 + tg + 4) * 136 + 8 * nt + g];
            mma_tf32(acc[nt], a0, a1, a2, a3, b0, b1v);
        }
    }
    #pragma unroll
    for (int nt = 0; nt < 8; nt++) {
        const int col = 8 * nt + 2 * tg;
        *reinterpret_cast<__half2*>(AccH + (rb + g) * 72 + col)
            = __floats2half2_rn(acc[nt][0], acc[nt][1]);
        *reinterpret_cast<__half2*>(AccH + (rb + g + 8) * 72 + col)
            = __floats2half2_rn(acc[nt][2], acc[nt][3]);
    }
    __syncthreads();

    // ---- pass 2: combine (gathers long since landed) + relu + fp32 scatter + deg ----
    #pragma unroll
    for (int p = 0; p < 8; p++) {
        const int r = p * 16 + rr;
        if (e0 + r < E) {
            float2 pa = __half22float2(*reinterpret_cast<__half2*>(&preu[p].x));
            float2 pb = __half22float2(*reinterpret_cast<__half2*>(&preu[p].y));
            float2 qa = __half22float2(*reinterpret_cast<__half2*>(&postu[p].x));
            float2 qb = __half22float2(*reinterpret_cast<__half2*>(&postu[p].y));
            uint2 au = *reinterpret_cast<const uint2*>(AccH + r * 72 + c4);
            float2 a01 = __half22float2(*reinterpret_cast<__half2*>(&au.x));
            float2 a23 = __half22float2(*reinterpret_cast<__half2*>(&au.y));
            float hx = fmaxf(pa.x + qa.x + a01.x, 0.f);
            float hy = fmaxf(pa.y + qa.y + a01.y, 0.f);
            float hz = fmaxf(pb.x + qb.x + a23.x, 0.f);
            float hw = fmaxf(pb.y + qb.y + a23.y, 0.f);
            red_add_v4(g_hsum + (size_t)dsts[p] * 64 + c4, hx, hy, hz, hw);
            if ((tid & 15) == 0) red_add_f32(g_deg + dsts[p], 1.0f);
        }
    }
}

// ================= K3: out = g_hsum @ W2 + deg (x) b2; re-zero AFTER all uses =================
__global__ __launch_bounds__(256, 3)
void k3_kernel(const float* __restrict__ W2, const float* __restrict__ b2,
               float* __restrict__ out, int M) {
    __shared__ uint32_t Ws[64 * 72];
    const int tid = threadIdx.x, lane = tid & 31, wid = tid >> 5;
    const int g = lane >> 2, tg = lane & 3;
    const int m0 = blockIdx.x * 128;

    for (int idx = tid; idx < 64 * 64; idx += 256) {
        int k = idx >> 6, n = idx & 63;
        Ws[k * 72 + n] = f2tf32(W2[idx]);
    }
    __syncthreads();

    const int rb = wid * 16;
    const int r0 = m0 + rb + g, r1 = r0 + 8;
    const float* h0 = g_hsum + (size_t)(r0 < M ? r0 : M - 1) * 64;
    const float* h1 = g_hsum + (size_t)(r1 < M ? r1 : M - 1) * 64;

    uint32_t afr[8][4];
    #pragma unroll
    for (int kt = 0; kt < 8; kt++) {
        const int k0 = kt * 8;
        afr[kt][0] = f2tf32(__ldg(h0 + k0 + tg));
        afr[kt][1] = f2tf32(__ldg(h1 + k0 + tg));
        afr[kt][2] = f2tf32(__ldg(h0 + k0 + tg + 4));
        afr[kt][3] = f2tf32(__ldg(h1 + k0 + tg + 4));
    }
    const float d0 = (r0 < M) ? g_deg[r0] : 0.f;
    const float d1 = (r1 < M) ? g_deg[r1] : 0.f;

    float acc[8][4];
    #pragma unroll
    for (int nt = 0; nt < 8; nt++) acc[nt][0] = acc[nt][1] = acc[nt][2] = acc[nt][3] = 0.f;

    #pragma unroll
    for (int kt = 0; kt < 8; kt++) {
        const int k0 = kt * 8;
        #pragma unroll
        for (int nt = 0; nt < 8; nt++) {
            uint32_t b0 = Ws[(k0 + tg) * 72 + 8 * nt + g];
            uint32_t b1v = Ws[(k0 + tg + 4) * 72 + 8 * nt + g];
            mma_tf32(acc[nt], afr[kt][0], afr[kt][1], afr[kt][2], afr[kt][3], b0, b1v);
        }
    }
    #pragma unroll
    for (int nt = 0; nt < 8; nt++) {
        const int col = 8 * nt + 2 * tg;
        const float bb0 = __ldg(b2 + col), bb1 = __ldg(b2 + col + 1);
        if (r0 < M) *reinterpret_cast<float2*>(out + (size_t)r0 * 64 + col)
                        = make_float2(acc[nt][0] + d0 * bb0, acc[nt][1] + d0 * bb1);
        if (r1 < M) *reinterpret_cast<float2*>(out + (size_t)r1 * 64 + col)
                        = make_float2(acc[nt][2] + d1 * bb0, acc[nt][3] + d1 * bb1);
    }

    // re-zero consumed state for the next graph replay. SAFE: the MMA loop consumed
    // every afr register and the output stores consumed d0/d1, so all loads from
    // g_hsum/g_deg are complete (true data dependence) before these stores issue.
    {
        const int zr = m0 + rb + (lane >> 1);
        if (zr < M) {
            float4* zp = reinterpret_cast<float4*>(g_hsum + (size_t)zr * 64 + (lane & 1) * 32);
            #pragma unroll
            for (int q = 0; q < 8; q++) zp[q] = make_float4(0.f, 0.f, 0.f, 0.f);
        }
        const int dr = m0 + rb + lane;
        if (lane < 16 && dr < M) g_deg[dr] = 0.f;
    }
}

// ---------------- launch ----------------
extern "C" void kernel_launch(void* const* d_in, const int* in_sizes, int n_in,
                              void* d_out, int out_size) {
    const float* x  = (const float*)d_in[0];
    const int*   ei = (const int*)d_in[1];      // int32 (JAX x64 disabled)
    const float* ea = (const float*)d_in[2];
    const float* W1 = (const float*)d_in[3];
    const float* b1 = (const float*)d_in[4];
    const float* W2 = (const float*)d_in[5];
    const float* b2 = (const float*)d_in[6];
    float* out = (float*)d_out;

    int E = in_sizes[1] / 2;
    int M = out_size / 64;
    int mtiles = (M + 127) / 128;
    int etiles = (E + 127) / 128;

    cudaFuncSetAttribute(k2_kernel, cudaFuncAttributeMaxDynamicSharedMemorySize, K2_SMEM);

    k1_kernel<<<mtiles, 256>>>(x, W1, b1, M);
    k2_kernel<<<etiles, 256, K2_SMEM>>>(ei, ea, W1, E);
    k3_kernel<<<mtiles, 256>>>(W2, b2, out, M);
}

// round 16
// speedup vs baseline: 1.1485x; 1.1485x over previous
#include <cuda_runtime.h>
#include <cuda_fp16.h>
#include <cstdint>

#define NN 50000
#define NE 800000

// ---------------- device scratch (zero-initialized at load; K3 restores zeros) ----------------
__device__ __half g_nmh[(size_t)NN * 128]; // fp16: [n][0:64]=x@W1a+b1, [n][64:128]=x@W1b
__device__ float  g_hsum[(size_t)NN * 64]; // fp32 per-node sum of relu(h)
__device__ float  g_deg[NN];               // per-node edge count

// ---------------- helpers ----------------
__device__ __forceinline__ uint32_t f2tf32(float f) {
    uint32_t r;
    asm("cvt.rna.tf32.f32 %0, %1;" : "=r"(r) : "f"(f));
    return r;
}
__device__ __forceinline__ uint4 f2tf32x4(float4 v) {
    uint4 u;
    u.x = f2tf32(v.x); u.y = f2tf32(v.y); u.z = f2tf32(v.z); u.w = f2tf32(v.w);
    return u;
}
__device__ __forceinline__ void mma_tf32(float c[4],
                                         uint32_t a0, uint32_t a1, uint32_t a2, uint32_t a3,
                                         uint32_t b0, uint32_t b1) {
    asm volatile(
        "mma.sync.aligned.m16n8k8.row.col.f32.tf32.tf32.f32 "
        "{%0,%1,%2,%3}, {%4,%5,%6,%7}, {%8,%9}, {%0,%1,%2,%3};"
        : "+f"(c[0]), "+f"(c[1]), "+f"(c[2]), "+f"(c[3])
        : "r"(a0), "r"(a1), "r"(a2), "r"(a3), "r"(b0), "r"(b1));
}
__device__ __forceinline__ void red_add_v4(float* p, float a, float b, float c, float d) {
    asm volatile("red.global.add.v4.f32 [%0], {%1, %2, %3, %4};"
        :: "l"(p), "f"(a), "f"(b), "f"(c), "f"(d) : "memory");
}
__device__ __forceinline__ void red_add_f32(float* p, float v) {
    asm volatile("red.global.add.f32 [%0], %1;" :: "l"(p), "f"(v) : "memory");
}

// ================= K1: g_nmh = fp16(x @ [W1a|W1b] (+b1)), single pass =================
__global__ __launch_bounds__(256)
void k1_kernel(const float* __restrict__ x, const float* __restrict__ W1,
               const float* __restrict__ b1, int M) {
    __shared__ uint32_t Ws[64 * 136];
    const int tid = threadIdx.x, lane = tid & 31, wid = tid >> 5;
    const int g = lane >> 2, tg = lane & 3;
    const int m0 = blockIdx.x * 128;

    // vectorized weight staging: 64 rows x 32 quads = 2048 float4s (8 per thread)
    for (int idx = tid; idx < 2048; idx += 256) {
        int k = idx >> 5, n4 = (idx & 31) * 4;       // k 0..63, n4 0..124
        float4 v = (n4 < 64)
            ? *reinterpret_cast<const float4*>(W1 + k * 64 + n4)
            : *reinterpret_cast<const float4*>(W1 + (64 + k) * 64 + (n4 - 64));
        *reinterpret_cast<uint4*>(Ws + k * 136 + n4) = f2tf32x4(v);
    }
    __syncthreads();

    const int rb = wid * 16;
    const int r0 = m0 + rb + g, r1 = r0 + 8;
    const float* xr0 = x + (size_t)(r0 < M ? r0 : M - 1) * 64;
    const float* xr1 = x + (size_t)(r1 < M ? r1 : M - 1) * 64;

    uint32_t afr[8][4];
    #pragma unroll
    for (int kt = 0; kt < 8; kt++) {
        const int k0 = kt * 8;
        afr[kt][0] = f2tf32(__ldg(xr0 + k0 + tg));
        afr[kt][1] = f2tf32(__ldg(xr1 + k0 + tg));
        afr[kt][2] = f2tf32(__ldg(xr0 + k0 + tg + 4));
        afr[kt][3] = f2tf32(__ldg(xr1 + k0 + tg + 4));
    }

    float acc[16][4];
    #pragma unroll
    for (int nt = 0; nt < 16; nt++) acc[nt][0] = acc[nt][1] = acc[nt][2] = acc[nt][3] = 0.f;

    #pragma unroll
    for (int kt = 0; kt < 8; kt++) {
        const int k0 = kt * 8;
        #pragma unroll
        for (int nt = 0; nt < 16; nt++) {
            uint32_t b0 = Ws[(k0 + tg) * 136 + 8 * nt + g];
            uint32_t b1v = Ws[(k0 + tg + 4) * 136 + 8 * nt + g];
            mma_tf32(acc[nt], afr[kt][0], afr[kt][1], afr[kt][2], afr[kt][3], b0, b1v);
        }
    }
    #pragma unroll
    for (int nt = 0; nt < 16; nt++) {
        const int col = 8 * nt + 2 * tg;
        float e0 = 0.f, e1 = 0.f;
        if (col < 64) { e0 = __ldg(b1 + col); e1 = __ldg(b1 + col + 1); }
        if (r0 < M)
            *reinterpret_cast<__half2*>(g_nmh + (size_t)r0 * 128 + col)
                = __floats2half2_rn(acc[nt][0] + e0, acc[nt][1] + e1);
        if (r1 < M)
            *reinterpret_cast<__half2*>(g_nmh + (size_t)r1 * 128 + col)
                = __floats2half2_rn(acc[nt][2] + e0, acc[nt][3] + e1);
    }
}

// ================= K2: h = relu(pre[src]+post[dst]+ea@W1e) -> fp32 scatter + deg =================
// smem words: Aea[128*20] | Wes[16*136] | AccH[128*72 halves = 4608 w] | Ssrc[128] | Sdst[128]
#define AEA_O  0
#define WES_O  (128 * 20)
#define ACCH_O (WES_O + 16 * 136)
#define SSRC_O (ACCH_O + 4608)
#define SDST_O (SSRC_O + 128)
#define K2_SMEM ((SDST_O + 128) * 4)   // 38400 B
__global__ __launch_bounds__(256, 3)
void k2_kernel(const int* __restrict__ ei, const float* __restrict__ ea,
               const float* __restrict__ W1, int E) {
    extern __shared__ float sm[];
    uint32_t* Aea = reinterpret_cast<uint32_t*>(sm) + AEA_O;
    uint32_t* Wes = reinterpret_cast<uint32_t*>(sm) + WES_O;
    __half*   AccH = reinterpret_cast<__half*>(sm + ACCH_O);
    int*      Ssrc = reinterpret_cast<int*>(sm) + SSRC_O;
    int*      Sdst = reinterpret_cast<int*>(sm) + SDST_O;

    const int tid = threadIdx.x, lane = tid & 31, wid = tid >> 5;
    const int g = lane >> 2, tg = lane & 3;
    const int e0 = blockIdx.x * 128;

    if (tid < 128) {
        int e = e0 + tid;
        Ssrc[tid] = (e < E) ? ei[e] : 0;
        Sdst[tid] = (e < E) ? ei[E + e] : 0;
    }
    #pragma unroll
    for (int p = 0; p < 2; p++) {
        int q = tid + 256 * p;            // 0..511
        int r = q >> 2, c = (q & 3) * 4;
        int e = e0 + r;
        float4 v = (e < E) ? __ldg(reinterpret_cast<const float4*>(ea + (size_t)e * 16 + c))
                           : make_float4(0.f, 0.f, 0.f, 0.f);
        *reinterpret_cast<uint4*>(Aea + r * 20 + c) = f2tf32x4(v);
    }
    {   // vectorized Wes staging: 16 rows x 16 quads = 256 float4s (1 per thread)
        int k = tid >> 4, n4 = (tid & 15) * 4;
        float4 v = *reinterpret_cast<const float4*>(W1 + (128 + k) * 64 + n4);
        *reinterpret_cast<uint4*>(Wes + k * 136 + n4) = f2tf32x4(v);
    }
    __syncthreads();

    // tiny MMA: acc = ea[128x16] @ W1e[16x64], stored fp16
    const int rb = wid * 16;
    float acc[8][4];
    #pragma unroll
    for (int nt = 0; nt < 8; nt++) acc[nt][0] = acc[nt][1] = acc[nt][2] = acc[nt][3] = 0.f;
    #pragma unroll
    for (int kt = 0; kt < 2; kt++) {
        const int k0 = kt * 8;
        uint32_t a0 = Aea[(rb + g) * 20 + k0 + tg];
        uint32_t a1 = Aea[(rb + g + 8) * 20 + k0 + tg];
        uint32_t a2 = Aea[(rb + g) * 20 + k0 + tg + 4];
        uint32_t a3 = Aea[(rb + g + 8) * 20 + k0 + tg + 4];
        #pragma unroll
        for (int nt = 0; nt < 8; nt++) {
            uint32_t b0 = Wes[(k0 + tg) * 136 + 8 * nt + g];
            uint32_t b1v = Wes[(k0 + tg + 4) * 136 + 8 * nt + g];
            mma_tf32(acc[nt], a0, a1, a2, a3, b0, b1v);
        }
    }
    #pragma unroll
    for (int nt = 0; nt < 8; nt++) {
        const int col = 8 * nt + 2 * tg;
        *reinterpret_cast<__half2*>(AccH + (rb + g) * 72 + col)
            = __floats2half2_rn(acc[nt][0], acc[nt][1]);
        *reinterpret_cast<__half2*>(AccH + (rb + g + 8) * 72 + col)
            = __floats2half2_rn(acc[nt][2], acc[nt][3]);
    }
    __syncthreads();

    // pass 2: batched fp16 gather (MLP=16) + relu + fp32 scatter + deg
    const int rr = tid >> 4;              // 0..15
    const int c4 = (tid & 15) * 4;        // col quad

    int srcs[8], dsts[8];
    #pragma unroll
    for (int p = 0; p < 8; p++) {
        const int r = p * 16 + rr;
        srcs[p] = Ssrc[r];
        dsts[p] = Sdst[r];
    }
    uint2 preu[8], postu[8];
    #pragma unroll
    for (int p = 0; p < 8; p++)
        preu[p]  = __ldg(reinterpret_cast<const uint2*>(g_nmh + (size_t)srcs[p] * 128 + c4));
    #pragma unroll
    for (int p = 0; p < 8; p++)
        postu[p] = __ldg(reinterpret_cast<const uint2*>(g_nmh + (size_t)dsts[p] * 128 + 64 + c4));

    #pragma unroll
    for (int p = 0; p < 8; p++) {
        const int r = p * 16 + rr;
        if (e0 + r < E) {
            float2 pa = __half22float2(*reinterpret_cast<__half2*>(&preu[p].x));
            float2 pb = __half22float2(*reinterpret_cast<__half2*>(&preu[p].y));
            float2 qa = __half22float2(*reinterpret_cast<__half2*>(&postu[p].x));
            float2 qb = __half22float2(*reinterpret_cast<__half2*>(&postu[p].y));
            uint2 au = *reinterpret_cast<const uint2*>(AccH + r * 72 + c4);
            float2 a01 = __half22float2(*reinterpret_cast<__half2*>(&au.x));
            float2 a23 = __half22float2(*reinterpret_cast<__half2*>(&au.y));
            float hx = fmaxf(pa.x + qa.x + a01.x, 0.f);
            float hy = fmaxf(pa.y + qa.y + a01.y, 0.f);
            float hz = fmaxf(pb.x + qb.x + a23.x, 0.f);
            float hw = fmaxf(pb.y + qb.y + a23.y, 0.f);
            red_add_v4(g_hsum + (size_t)dsts[p] * 64 + c4, hx, hy, hz, hw);
            if ((tid & 15) == 0) red_add_f32(g_deg + dsts[p], 1.0f);
        }
    }
}

// ================= K3: out = g_hsum @ W2 + deg (x) b2; re-zero AFTER all uses =================
__global__ __launch_bounds__(256, 3)
void k3_kernel(const float* __restrict__ W2, const float* __restrict__ b2,
               float* __restrict__ out, int M) {
    __shared__ uint32_t Ws[64 * 72];
    const int tid = threadIdx.x, lane = tid & 31, wid = tid >> 5;
    const int g = lane >> 2, tg = lane & 3;
    const int m0 = blockIdx.x * 128;

    // vectorized staging: 64 rows x 16 quads = 1024 float4s (4 per thread)
    for (int idx = tid; idx < 1024; idx += 256) {
        int k = idx >> 4, n4 = (idx & 15) * 4;       // k 0..63, n4 0..60
        float4 v = *reinterpret_cast<const float4*>(W2 + k * 64 + n4);
        *reinterpret_cast<uint4*>(Ws + k * 72 + n4) = f2tf32x4(v);
    }
    __syncthreads();

    const int rb = wid * 16;
    const int r0 = m0 + rb + g, r1 = r0 + 8;
    const float* h0 = g_hsum + (size_t)(r0 < M ? r0 : M - 1) * 64;
    const float* h1 = g_hsum + (size_t)(r1 < M ? r1 : M - 1) * 64;

    uint32_t afr[8][4];
    #pragma unroll
    for (int kt = 0; kt < 8; kt++) {
        const int k0 = kt * 8;
        afr[kt][0] = f2tf32(__ldg(h0 + k0 + tg));
        afr[kt][1] = f2tf32(__ldg(h1 + k0 + tg));
        afr[kt][2] = f2tf32(__ldg(h0 + k0 + tg + 4));
        afr[kt][3] = f2tf32(__ldg(h1 + k0 + tg + 4));
    }
    const float d0 = (r0 < M) ? g_deg[r0] : 0.f;
    const float d1 = (r1 < M) ? g_deg[r1] : 0.f;

    float acc[8][4];
    #pragma unroll
    for (int nt = 0; nt < 8; nt++) acc[nt][0] = acc[nt][1] = acc[nt][2] = acc[nt][3] = 0.f;

    #pragma unroll
    for (int kt = 0; kt < 8; kt++) {
        const int k0 = kt * 8;
        #pragma unroll
        for (int nt = 0; nt < 8; nt++) {
            uint32_t b0 = Ws[(k0 + tg) * 72 + 8 * nt + g];
            uint32_t b1v = Ws[(k0 + tg + 4) * 72 + 8 * nt + g];
            mma_tf32(acc[nt], afr[kt][0], afr[kt][1], afr[kt][2], afr[kt][3], b0, b1v);
        }
    }
    #pragma unroll
    for (int nt = 0; nt < 8; nt++) {
        const int col = 8 * nt + 2 * tg;
        const float bb0 = __ldg(b2 + col), bb1 = __ldg(b2 + col + 1);
        if (r0 < M) *reinterpret_cast<float2*>(out + (size_t)r0 * 64 + col)
                        = make_float2(acc[nt][0] + d0 * bb0, acc[nt][1] + d0 * bb1);
        if (r1 < M) *reinterpret_cast<float2*>(out + (size_t)r1 * 64 + col)
                        = make_float2(acc[nt][2] + d1 * bb0, acc[nt][3] + d1 * bb1);
    }

    // re-zero consumed state for the next graph replay. SAFE: the MMA loop consumed
    // every afr register and the output stores consumed d0/d1, so all loads from
    // g_hsum/g_deg are complete (true data dependence) before these stores issue.
    {
        const int zr = m0 + rb + (lane >> 1);
        if (zr < M) {
            float4* zp = reinterpret_cast<float4*>(g_hsum + (size_t)zr * 64 + (lane & 1) * 32);
            #pragma unroll
            for (int q = 0; q < 8; q++) zp[q] = make_float4(0.f, 0.f, 0.f, 0.f);
        }
        const int dr = m0 + rb + lane;
        if (lane < 16 && dr < M) g_deg[dr] = 0.f;
    }
}

// ---------------- launch ----------------
extern "C" void kernel_launch(void* const* d_in, const int* in_sizes, int n_in,
                              void* d_out, int out_size) {
    const float* x  = (const float*)d_in[0];
    const int*   ei = (const int*)d_in[1];      // int32 (JAX x64 disabled)
    const float* ea = (const float*)d_in[2];
    const float* W1 = (const float*)d_in[3];
    const float* b1 = (const float*)d_in[4];
    const float* W2 = (const float*)d_in[5];
    const float* b2 = (const float*)d_in[6];
    float* out = (float*)d_out;

    int E = in_sizes[1] / 2;
    int M = out_size / 64;
    int mtiles = (M + 127) / 128;
    int etiles = (E + 127) / 128;

    cudaFuncSetAttribute(k2_kernel, cudaFuncAttributeMaxDynamicSharedMemorySize, K2_SMEM);

    k1_kernel<<<mtiles, 256>>>(x, W1, b1, M);
    k2_kernel<<<etiles, 256, K2_SMEM>>>(ei, ea, W1, E);
    k3_kernel<<<mtiles, 256>>>(W2, b2, out, M);
}